// round 12
// baseline (speedup 1.0000x reference)
#include <cuda_runtime.h>
#include <cuda_bf16.h>
#include <math.h>

// ============================================================================
// FamNet pipeline. bf16 split mma convs (MR=8 stride-1) + fused tail.
// ============================================================================

#define NB 2
#define NP 3

// ---------------- device scratch (no allocations allowed) -------------------
__device__ float g_x1[2 * 64 * 192 * 192];
__device__ float g_x2[2 * 256 * 96 * 96];
__device__ float g_f3[2 * 512 * 48 * 48];
__device__ float g_f4[2 * 1024 * 24 * 24];
__device__ float g_patches[2 * 3 * 1024 * 576];
__device__ float g_pf[2 * 3 * 3 * 1024 * 1024];
__device__ float g_simtmp[2 * 2 * 3 * 3 * 2304];
__device__ float g_sims[2 * 3 * 6 * 48 * 48];
__device__ float g_r1[6 * 196 * 48 * 48];
__device__ float g_u1[6 * 196 * 96 * 96];
__device__ float g_r2[6 * 128 * 96 * 96];
__device__ float g_u2[6 * 128 * 192 * 192];
__device__ float g_r3[6 * 64 * 192 * 192];
__device__ float g_wbuf[64 * 49 * 64];                // scalar-path weights (fw1 only)
__device__ uint4 g_wq[1200000];                       // mma-path weights

// ---------------- box / scale metadata --------------------------------------
__device__ int g_tl[2][2][3][2];
__device__ int g_crop[2][2][3][2];
__device__ int g_PH[2][2], g_PW[2][2];
__device__ int g_PHs[2][2][3], g_PWs[2][2][3];

__global__ void meta_kernel(const float* __restrict__ tlbrs) {
    if (threadIdx.x != 0 || blockIdx.x != 0) return;
    const double scales[3] = {1.0, 0.9, 1.1};
    for (int b = 0; b < NB; b++) {
        for (int L = 0; L < 2; L++) {
            int F = (L == 0) ? 48 : 24;
            float inv = (float)F / 384.0f;
            int maxh = 0, maxw = 0;
            for (int p = 0; p < NP; p++) {
                const float* v = tlbrs + (b * NP + p) * 4;
                float sct = v[0] * inv, scl = v[1] * inv;
                float scb = v[2] * inv, scr = v[3] * inv;
                int top = (int)floorf(sct); if (top < 0) top = 0;
                int left = (int)floorf(scl); if (left < 0) left = 0;
                int bot = (int)ceilf(scb) + 1; if (bot > F) bot = F;
                int right = (int)ceilf(scr) + 1; if (right > F) right = F;
                g_tl[b][L][p][0] = top;  g_tl[b][L][p][1] = left;
                g_crop[b][L][p][0] = bot - top;  g_crop[b][L][p][1] = right - left;
                if (bot - top > maxh) maxh = bot - top;
                if (right - left > maxw) maxw = right - left;
            }
            g_PH[b][L] = maxh; g_PW[b][L] = maxw;
            for (int s = 0; s < 3; s++) {
                int ph = (int)ceil((double)maxh * scales[s]);
                int pw = (int)ceil((double)maxw * scales[s]);
                if (ph < 1) ph = maxh;
                if (pw < 1) pw = maxw;
                g_PHs[b][L][s] = ph; g_PWs[b][L][s] = pw;
            }
        }
    }
}

// ---------------- helpers ----------------------------------------------------
__device__ __forceinline__ unsigned pk(float a, float b) {
    unsigned ha = (unsigned)__bfloat16_as_ushort(__float2bfloat16_rn(a));
    unsigned hb = (unsigned)__bfloat16_as_ushort(__float2bfloat16_rn(b));
    return ha | (hb << 16);
}
__device__ __forceinline__ float bhi(float v) {
    return __bfloat162float(__float2bfloat16_rn(v));
}

#define MMA(d, a, bb0, bb1)                                                       \
    asm volatile("mma.sync.aligned.m16n8k16.row.col.f32.bf16.bf16.f32 "           \
                 "{%0,%1,%2,%3},{%4,%5,%6,%7},{%8,%9},{%0,%1,%2,%3};"             \
                 : "+f"(d[0]), "+f"(d[1]), "+f"(d[2]), "+f"(d[3])                 \
                 : "r"(a[0]), "r"(a[1]), "r"(a[2]), "r"(a[3]), "r"(bb0), "r"(bb1))

// ---------------- mma weight transform ---------------------------------------
__global__ void wq_kernel(const float* __restrict__ wt, uint4* __restrict__ wq,
                          int Cin, int Cout, int K2, int ntiles, int total) {
    int idx = blockIdx.x * blockDim.x + threadIdx.x;
    if (idx >= total) return;
    int lane = idx & 31;
    int nt = (idx >> 5) % ntiles;
    int t = idx / (32 * ntiles);
    int chunk = t / K2, tl = t - chunk * K2;
    int n = nt * 8 + (lane >> 2);
    int kf0 = (lane & 3) * 2;

    float w[4], whi[4];
#pragma unroll
    for (int j = 0; j < 4; j++) {
        int kf = kf0 + (j >> 1) * 8 + (j & 1);
        int ci = chunk * 16 + kf;
        w[j] = (ci < Cin && n < Cout) ? __ldg(wt + ((size_t)n * Cin + ci) * K2 + tl) : 0.0f;
        whi[j] = bhi(w[j]);
    }
    uint4 o;
    o.x = pk(whi[0], whi[1]);
    o.y = pk(whi[2], whi[3]);
    o.z = pk(w[0] - whi[0], w[1] - whi[1]);
    o.w = pk(w[2] - whi[2], w[3] - whi[3]);
    wq[idx] = o;
}

// ---------------- mma conv: 32x(MR) px x (NT*8) couts ------------------------
// MR=8: each warp computes 2 m16 tiles (rows y, y+4) sharing weight loads.
template <int K, int STRIDE, int NT, int MR>
__global__ void __launch_bounds__(256)
conv_mma(const float* __restrict__ in, const uint4* __restrict__ wq,
         const float* __restrict__ bias, float* __restrict__ out,
         int N, int Cin, int Hin, int Win, int Cout, int Hout, int Wout,
         int pad, int relu, int cotiles, int chunks, int ntiles) {
    constexpr int K2 = K * K;
    constexpr int MT = MR / 4;
    constexpr int IH = (MR - 1) * STRIDE + K;
    constexpr int IW = 31 * STRIDE + K;
    constexpr int NPX = IH * IW;

    __shared__ unsigned s_hi[NPX][8];
    __shared__ unsigned s_lo[NPX][8];

    const int tid = threadIdx.x;
    const int lane = tid & 31;
    const int wm = tid >> 5;

    const int bx = blockIdx.x, by = blockIdx.y;
    const int n = blockIdx.z / cotiles;
    const int co0 = (blockIdx.z % cotiles) * (NT * 8);

    const int ix0 = bx * 32 * STRIDE - pad;
    const int iy0 = by * MR * STRIDE - pad;

    const int y = wm >> 1;
    const int r = lane >> 2;
    const int xA = ((wm & 1) << 4) + r;
    const int pcL = lane & 3;
    const int c0 = pcL * 2;

    float acc[MT][NT][4];
#pragma unroll
    for (int m = 0; m < MT; m++)
#pragma unroll
        for (int i = 0; i < NT; i++)
#pragma unroll
            for (int j = 0; j < 4; j++) acc[m][i][j] = 0.0f;

    const size_t in_n = (size_t)n * Cin * Hin * Win;
    const size_t HW = (size_t)Hin * Win;

    for (int chunk = 0; chunk < chunks; chunk++) {
        for (int i = tid; i < 8 * NPX; i += 256) {
            int pc = i / NPX;
            int rem = i - pc * NPX;
            int rr = rem / IW, cc = rem - rr * IW;
            int gy = iy0 + rr, gx = ix0 + cc;
            int ci0 = chunk * 16 + pc * 2;
            float f0 = 0.0f, f1 = 0.0f;
            if ((unsigned)gy < (unsigned)Hin && (unsigned)gx < (unsigned)Win) {
                const float* p = in + in_n + (size_t)gy * Win + gx;
                if (ci0 < Cin)     f0 = __ldg(p + (size_t)ci0 * HW);
                if (ci0 + 1 < Cin) f1 = __ldg(p + (size_t)(ci0 + 1) * HW);
            }
            float h0 = bhi(f0), h1 = bhi(f1);
            int sw = (pc + rem) & 7;
            s_hi[rem][sw] = pk(h0, h1);
            s_lo[rem][sw] = pk(f0 - h0, f1 - h1);
        }
        __syncthreads();

#pragma unroll 1
        for (int tl = 0; tl < K2; tl++) {
            int kh = tl / K, kw = tl - kh * K;

            unsigned ahi[MT][4], alo[MT][4];
#pragma unroll
            for (int m = 0; m < MT; m++) {
                int pixA = ((y + m * 4) * STRIDE + kh) * IW + kw + xA * STRIDE;
                int pixB = pixA + 8 * STRIDE;
                ahi[m][0] = s_hi[pixA][(pcL + pixA) & 7];
                ahi[m][1] = s_hi[pixB][(pcL + pixB) & 7];
                ahi[m][2] = s_hi[pixA][(pcL + 4 + pixA) & 7];
                ahi[m][3] = s_hi[pixB][(pcL + 4 + pixB) & 7];
                alo[m][0] = s_lo[pixA][(pcL + pixA) & 7];
                alo[m][1] = s_lo[pixB][(pcL + pixB) & 7];
                alo[m][2] = s_lo[pixA][(pcL + 4 + pixA) & 7];
                alo[m][3] = s_lo[pixB][(pcL + 4 + pixB) & 7];
            }

            int tg = chunk * K2 + tl;
            const uint4* wrow = wq + ((size_t)tg * ntiles + (co0 >> 3)) * 32 + lane;
#pragma unroll
            for (int nt = 0; nt < NT; nt++) {
                uint4 wv = __ldg(wrow + nt * 32);
#pragma unroll
                for (int m = 0; m < MT; m++) {
                    MMA(acc[m][nt], ahi[m], wv.x, wv.y);   // hi*hi
                    MMA(acc[m][nt], ahi[m], wv.z, wv.w);   // hi*lo
                    MMA(acc[m][nt], alo[m], wv.x, wv.y);   // lo*hi
                }
            }
        }
        __syncthreads();
    }

#pragma unroll
    for (int m = 0; m < MT; m++) {
        const int oy = by * MR + y + m * 4;
        if (oy >= Hout) continue;
#pragma unroll
        for (int half = 0; half < 2; half++) {
            int ox = bx * 32 + xA + half * 8;
            if (ox >= Wout) continue;
#pragma unroll
            for (int nt = 0; nt < NT; nt++) {
#pragma unroll
                for (int e = 0; e < 2; e++) {
                    int co = co0 + nt * 8 + c0 + e;
                    if (co >= Cout) continue;
                    float v = acc[m][nt][half * 2 + e];
                    if (bias) v += __ldg(bias + co);
                    if (relu) v = fmaxf(v, 0.0f);
                    out[(((size_t)n * Cout + co) * Hout + oy) * Wout + ox] = v;
                }
            }
        }
    }
}

// ---------------- scalar weight transpose (fw1 only) -------------------------
__global__ void wtrans_kernel(const float* __restrict__ wt, float* __restrict__ wbuf,
                              int Cin, int Cout, int Co_pad, int K2, int total) {
    int idx = blockIdx.x * blockDim.x + threadIdx.x;
    if (idx >= total) return;
    int co = idx % Co_pad;
    int t = idx / Co_pad;
    int kk = t % K2;
    int ci = t / K2;
    wbuf[idx] = (co < Cout) ? __ldg(wt + ((size_t)co * Cin + ci) * K2 + kk) : 0.0f;
}

// ---------------- scalar conv (fw1 only: K=7, S=2) ---------------------------
template <int K, int STRIDE>
__global__ void conv_tiled2(const float* __restrict__ in, const float* __restrict__ wbuf,
                            const float* __restrict__ bias, float* __restrict__ out,
                            int N, int Cin, int Hin, int Win,
                            int Cout, int Co_pad, int Hout, int Wout,
                            int pad, int relu, int cotiles) {
    constexpr int K2 = K * K;
    constexpr int IH = 3 * STRIDE + K;
    constexpr int IW = 31 * STRIDE + K;

    __shared__ float s_in[IH * IW];
    __shared__ float4 s_w[K2 * 8];

    const int tid = threadIdx.x;
    const int tx = tid & 15;
    const int ty = (tid >> 4) & 1;
    const int tc = tid >> 5;

    const int bx = blockIdx.x, by = blockIdx.y;
    const int n   = blockIdx.z / cotiles;
    const int co0 = (blockIdx.z % cotiles) * 32;

    const int ix0 = bx * 32 * STRIDE - pad;
    const int iy0 = by * 4 * STRIDE - pad;

    float acc[2][2][4] = {};
    const size_t in_n = (size_t)n * Cin * Hin * Win;

    for (int ci = 0; ci < Cin; ci++) {
        __syncthreads();
        const float* ip = in + in_n + (size_t)ci * Hin * Win;
#pragma unroll 2
        for (int i = tid; i < IH * IW; i += 256) {
            int r = i / IW, c = i - r * IW;
            int gy = iy0 + r, gx = ix0 + c;
            float v = 0.0f;
            if ((unsigned)gy < (unsigned)Hin && (unsigned)gx < (unsigned)Win)
                v = __ldg(ip + (size_t)gy * Win + gx);
            s_in[i] = v;
        }
        const float* wp = wbuf + (size_t)ci * K2 * Co_pad + co0;
#pragma unroll 2
        for (int i = tid; i < K2 * 32; i += 256) {
            int kk = i >> 5, c = i & 31;
            ((float*)s_w)[i] = __ldg(wp + kk * Co_pad + c);
        }
        __syncthreads();

#pragma unroll
        for (int kh = 0; kh < K; kh++) {
#pragma unroll
            for (int kw = 0; kw < K; kw++) {
                float4 w = s_w[(kh * K + kw) * 8 + tc];
                float iv[2][2];
#pragma unroll
                for (int yy = 0; yy < 2; yy++)
#pragma unroll
                    for (int xx = 0; xx < 2; xx++)
                        iv[yy][xx] = s_in[((2 * ty + yy) * STRIDE + kh) * IW
                                          + (2 * tx + xx) * STRIDE + kw];
#pragma unroll
                for (int yy = 0; yy < 2; yy++)
#pragma unroll
                    for (int xx = 0; xx < 2; xx++) {
                        acc[yy][xx][0] = fmaf(iv[yy][xx], w.x, acc[yy][xx][0]);
                        acc[yy][xx][1] = fmaf(iv[yy][xx], w.y, acc[yy][xx][1]);
                        acc[yy][xx][2] = fmaf(iv[yy][xx], w.z, acc[yy][xx][2]);
                        acc[yy][xx][3] = fmaf(iv[yy][xx], w.w, acc[yy][xx][3]);
                    }
            }
        }
    }

    const int ox = bx * 32 + 2 * tx;
    if (ox >= Wout) return;
#pragma unroll
    for (int c = 0; c < 4; c++) {
        int co = co0 + tc * 4 + c;
        if (co >= Cout) continue;
        float bv = bias ? __ldg(bias + co) : 0.0f;
#pragma unroll
        for (int yy = 0; yy < 2; yy++) {
            int oy = by * 4 + 2 * ty + yy;
            if (oy >= Hout) continue;
            float v0 = acc[yy][0][c] + bv;
            float v1 = acc[yy][1][c] + bv;
            if (relu) { v0 = fmaxf(v0, 0.0f); v1 = fmaxf(v1, 0.0f); }
            *(float2*)(out + (((size_t)n * Cout + co) * Hout + oy) * Wout + ox)
                = make_float2(v0, v1);
        }
    }
}

// ---------------- patch extraction -------------------------------------------
__global__ void extract_patches_all(const float* __restrict__ fmbase, float* __restrict__ patches,
                                    int C, int F, int L) {
    int idx = blockIdx.x * blockDim.x + threadIdx.x;
    int total = NB * NP * C * 576;
    if (idx >= total) return;
    int ox = idx % 24;
    int oy = (idx / 24) % 24;
    int c = (idx / 576) % C;
    int p = (idx / (576 * C)) % NP;
    int b = idx / (576 * C * NP);
    int PH = g_PH[b][L], PW = g_PW[b][L];
    if (oy >= PH || ox >= PW) return;
    int top = g_tl[b][L][p][0], left = g_tl[b][L][p][1];
    int h = g_crop[b][L][p][0], w = g_crop[b][L][p][1];

    float sy = ((float)oy + 0.5f) * ((float)h / (float)PH) - 0.5f;
    if (sy < 0.0f) sy = 0.0f;
    float sx = ((float)ox + 0.5f) * ((float)w / (float)PW) - 0.5f;
    if (sx < 0.0f) sx = 0.0f;
    int y0 = (int)sy; float ty = sy - (float)y0;
    int x0 = (int)sx; float tx = sx - (float)x0;
    if (y0 > h - 1) { y0 = h - 1; ty = 0.0f; }
    if (x0 > w - 1) { x0 = w - 1; tx = 0.0f; }
    int y1 = min(y0 + 1, h - 1);
    int x1 = min(x0 + 1, w - 1);

    const float* base = fmbase + (size_t)b * C * F * F + ((size_t)c * F + top) * F + left;
    float v00 = base[y0 * F + x0], v01 = base[y0 * F + x1];
    float v10 = base[y1 * F + x0], v11 = base[y1 * F + x1];
    float val = v00 * (1.0f - ty) * (1.0f - tx) + v01 * (1.0f - ty) * tx
              + v10 * ty * (1.0f - tx) + v11 * ty * tx;
    patches[((size_t)((b * NP + p) * C + c)) * 576 + oy * 24 + ox] = val;
}

__global__ void resize_pf_all(const float* __restrict__ patches, float* __restrict__ pf,
                              int C, int L) {
    int idx = blockIdx.x * blockDim.x + threadIdx.x;
    int total = NB * 3 * NP * C * 1024;
    if (idx >= total) return;
    int ox = idx & 31;
    int oy = (idx >> 5) & 31;
    int c = (idx >> 10) % C;
    int rest = idx / (1024 * C);
    int p = rest % NP;
    int s = (rest / NP) % 3;
    int b = rest / (NP * 3);

    int PHs = g_PHs[b][L][s], PWs = g_PWs[b][L][s];
    if (oy >= PHs || ox >= PWs) return;
    int PH = g_PH[b][L], PW = g_PW[b][L];

    float sy = ((float)oy + 0.5f) * ((float)PH / (float)PHs) - 0.5f;
    if (sy < 0.0f) sy = 0.0f;
    float sx = ((float)ox + 0.5f) * ((float)PW / (float)PWs) - 0.5f;
    if (sx < 0.0f) sx = 0.0f;
    int y0 = (int)sy; float ty = sy - (float)y0;
    int x0 = (int)sx; float tx = sx - (float)x0;
    if (y0 > PH - 1) { y0 = PH - 1; ty = 0.0f; }
    if (x0 > PW - 1) { x0 = PW - 1; tx = 0.0f; }
    int y1 = min(y0 + 1, PH - 1);
    int x1 = min(x0 + 1, PW - 1);

    const float* base = patches + ((size_t)((b * NP + p) * C + c)) * 576;
    float v00 = base[y0 * 24 + x0], v01 = base[y0 * 24 + x1];
    float v10 = base[y1 * 24 + x0], v11 = base[y1 * 24 + x1];
    float val = v00 * (1.0f - ty) * (1.0f - tx) + v01 * (1.0f - ty) * tx
              + v10 * ty * (1.0f - tx) + v11 * ty * tx;
    pf[((size_t)(((b * 3 + s) * NP + p) * C + c) << 10) + oy * 32 + ox] = val;
}

__global__ void zero_kernel(float* __restrict__ buf, int n) {
    int idx = blockIdx.x * blockDim.x + threadIdx.x;
    if (idx < n) buf[idx] = 0.0f;
}

// ---------------- tiled correlation ------------------------------------------
__global__ void __launch_bounds__(256)
sim_tiled(const float* __restrict__ fmbase, const float* __restrict__ pf,
          float* __restrict__ simtmp, int C, int F, int L, int nchunks, int cpc) {
    __shared__ float s_fm[63 * 64];
    __shared__ float s_pf[3][16 * 32];

    const int tid = threadIdx.x;
    const int tx = tid & 15, ty = tid >> 4;

    int chunk = blockIdx.x % nchunks;
    int bs = blockIdx.x / nchunks;
    int b = bs / 3, s = bs % 3;

    int PHs = g_PHs[b][L][s], PWs = g_PWs[b][L][s];
    int padT = PHs >> 1, padL = PWs >> 1;

    const int FF = F * F;
    const float* fm = fmbase + (size_t)b * C * FF;
    const float* pfb = pf + ((size_t)(bs * NP) * C << 10);
    int c0 = chunk * cpc;

    float acc[3][3][3];
#pragma unroll
    for (int p = 0; p < 3; p++)
#pragma unroll
        for (int ry = 0; ry < 3; ry++)
#pragma unroll
            for (int rx = 0; rx < 3; rx++) acc[p][ry][rx] = 0.0f;

    const int iy0 = -padT, ix0 = -padL;
    const int pfrows = PHs * 32;

    for (int c = c0; c < c0 + cpc; c++) {
        __syncthreads();
        const float* fmc = fm + (size_t)c * FF;
        for (int i = tid; i < 63 * 64; i += 256) {
            int r = i >> 6, cc = i & 63;
            int gy = iy0 + r, gx = ix0 + cc;
            float v = 0.0f;
            if ((unsigned)gy < (unsigned)F && (unsigned)gx < (unsigned)F)
                v = __ldg(fmc + gy * F + gx);
            s_fm[i] = v;
        }
        for (int i = tid; i < 3 * pfrows; i += 256) {
            int p = i / pfrows;
            int rem = i - p * pfrows;
            s_pf[p][rem] = __ldg(pfb + (((size_t)(p * C + c)) << 10) + rem);
        }
        __syncthreads();

        for (int i = 0; i < PHs; i++) {
            const float* fr = &s_fm[(ty + i) * 64 + tx];
            const float* p0 = &s_pf[0][i * 32];
            const float* p1 = &s_pf[1][i * 32];
            const float* p2 = &s_pf[2][i * 32];
            for (int j = 0; j < PWs; j++) {
                float w0 = p0[j], w1 = p1[j], w2 = p2[j];
                float v[3][3];
#pragma unroll
                for (int ry = 0; ry < 3; ry++)
#pragma unroll
                    for (int rx = 0; rx < 3; rx++)
                        v[ry][rx] = fr[(ry * 16) * 64 + rx * 16 + j];
#pragma unroll
                for (int ry = 0; ry < 3; ry++)
#pragma unroll
                    for (int rx = 0; rx < 3; rx++) {
                        acc[0][ry][rx] = fmaf(v[ry][rx], w0, acc[0][ry][rx]);
                        acc[1][ry][rx] = fmaf(v[ry][rx], w1, acc[1][ry][rx]);
                        acc[2][ry][rx] = fmaf(v[ry][rx], w2, acc[2][ry][rx]);
                    }
            }
        }
    }

#pragma unroll
    for (int p = 0; p < 3; p++) {
        float* dst = simtmp + (size_t)(((b * 2 + L) * 3 + s) * NP + p) * 2304;
#pragma unroll
        for (int ry = 0; ry < 3; ry++) {
            int y = ty + ry * 16;
            if (y >= F) continue;
#pragma unroll
            for (int rx = 0; rx < 3; rx++) {
                int x = tx + rx * 16;
                if (x >= F) continue;
                atomicAdd(dst + y * F + x, acc[p][ry][rx]);
            }
        }
    }
}

__global__ void sim_resize_all(const float* __restrict__ simtmp, float* __restrict__ sims) {
    int idx = blockIdx.x * blockDim.x + threadIdx.x;
    int total = NB * 2 * 3 * NP * 2304;
    if (idx >= total) return;
    int x = idx % 48;
    int y = (idx / 48) % 48;
    int p = (idx / 2304) % NP;
    int s = (idx / (2304 * NP)) % 3;
    int L = (idx / (2304 * NP * 3)) % 2;
    int b = idx / (2304 * NP * 3 * 2);
    int F = L ? 24 : 48;

    float sy = ((float)y + 0.5f) * ((float)F / 48.0f) - 0.5f;
    if (sy < 0.0f) sy = 0.0f;
    float sx = ((float)x + 0.5f) * ((float)F / 48.0f) - 0.5f;
    if (sx < 0.0f) sx = 0.0f;
    int y0 = (int)sy; float ty = sy - (float)y0;
    int x0 = (int)sx; float tx = sx - (float)x0;
    if (y0 > F - 1) { y0 = F - 1; ty = 0.0f; }
    if (x0 > F - 1) { x0 = F - 1; tx = 0.0f; }
    int y1 = min(y0 + 1, F - 1);
    int x1 = min(x0 + 1, F - 1);

    const float* base = simtmp + (size_t)(((b * 2 + L) * 3 + s) * NP + p) * 2304;
    float v00 = base[y0 * F + x0], v01 = base[y0 * F + x1];
    float v10 = base[y1 * F + x0], v11 = base[y1 * F + x1];
    float val = v00 * (1.0f - ty) * (1.0f - tx) + v01 * (1.0f - ty) * tx
              + v10 * ty * (1.0f - tx) + v11 * ty * tx;
    int ch = L * 3 + s;
    sims[((size_t)(b * NP + p) * 6 + ch) * 2304 + y * 48 + x] = val;
}

// ---------------- align-corners 2x bilinear upsample (u1, u2) ----------------
__global__ void upsample_kernel(const float* __restrict__ in, float* __restrict__ out,
                                int NC, int h, int w) {
    int H = 2 * h, W = 2 * w;
    int idx = blockIdx.x * blockDim.x + threadIdx.x;
    int total = NC * H * W;
    if (idx >= total) return;
    int ox = idx % W;
    int oy = (idx / W) % H;
    int nc = idx / (H * W);

    float stepy = (float)(h - 1) / (float)(H - 1);
    float stepx = (float)(w - 1) / (float)(W - 1);
    float py = (float)oy * stepy;
    float px = (float)ox * stepx;
    int y0 = (int)py; float ty = py - (float)y0;
    int x0 = (int)px; float tx = px - (float)x0;
    if (y0 > h - 1) { y0 = h - 1; ty = 0.0f; }
    if (x0 > w - 1) { x0 = w - 1; tx = 0.0f; }
    int y1 = min(y0 + 1, h - 1);
    int x1 = min(x0 + 1, w - 1);

    const float* ib = in + (size_t)nc * h * w;
    float v00 = ib[y0 * w + x0], v01 = ib[y0 * w + x1];
    float v10 = ib[y1 * w + x0], v11 = ib[y1 * w + x1];
    out[idx] = v00 * (1.0f - ty) * (1.0f - tx) + v01 * (1.0f - ty) * tx
             + v10 * ty * (1.0f - tx) + v11 * ty * tx;
}

// ---------------- fused: up2x(r3) -> rw4 1x1 relu -> rw5 1x1 relu -> max ----
// grid (24,24,6); block 256 = 16x16 out px; atomicMax into zeroed out.
__global__ void __launch_bounds__(256)
tail_fused(const float* __restrict__ r3, const float* __restrict__ w4,
           const float* __restrict__ b4, const float* __restrict__ w5,
           const float* __restrict__ b5, float* __restrict__ out) {
    __shared__ float s_r3[64][10][10];
    __shared__ float s_w4[32][64];
    __shared__ float s_w5[32];
    __shared__ float s_b4[32];

    const int tid = threadIdx.x;
    const int bp = blockIdx.z;
    const int b = bp / NP;
    const int ox0 = blockIdx.x * 16, oy0 = blockIdx.y * 16;
    const float f = 191.0f / 383.0f;

    int iy0 = (int)floorf((float)oy0 * f);
    int ix0 = (int)floorf((float)ox0 * f);

    for (int i = tid; i < 2048; i += 256)
        s_w4[i >> 6][i & 63] = __ldg(w4 + i);
    if (tid < 32) { s_w5[tid] = __ldg(w5 + tid); s_b4[tid] = __ldg(b4 + tid); }

    const float* src = r3 + (size_t)bp * 64 * 192 * 192;
    for (int i = tid; i < 64 * 100; i += 256) {
        int c = i / 100;
        int rem = i - c * 100;
        int ry = rem / 10, rx = rem - ry * 10;
        int gy = iy0 + ry, gx = ix0 + rx;
        float v = 0.0f;
        if (gy < 192 && gx < 192)
            v = __ldg(src + ((size_t)c * 192 + gy) * 192 + gx);
        s_r3[c][ry][rx] = v;
    }
    __syncthreads();

    const int ox = ox0 + (tid & 15);
    const int oy = oy0 + (tid >> 4);

    float py = (float)oy * f;
    float px = (float)ox * f;
    int y0 = (int)py; float ty = py - (float)y0;
    int x0 = (int)px; float tx = px - (float)x0;
    if (y0 > 191) { y0 = 191; ty = 0.0f; }
    if (x0 > 191) { x0 = 191; tx = 0.0f; }
    int y1 = min(y0 + 1, 191);
    int x1 = min(x0 + 1, 191);

    int ly = y0 - iy0, lx = x0 - ix0;
    int ly1 = y1 - iy0, lx1 = x1 - ix0;

    float w00 = (1.0f - ty) * (1.0f - tx), w01 = (1.0f - ty) * tx;
    float w10 = ty * (1.0f - tx), w11 = ty * tx;

    float acc[32];
#pragma unroll
    for (int c2 = 0; c2 < 32; c2++) acc[c2] = s_b4[c2];

    for (int c = 0; c < 64; c++) {
        float v = s_r3[c][ly][lx] * w00 + s_r3[c][ly][lx1] * w01
                + s_r3[c][ly1][lx] * w10 + s_r3[c][ly1][lx1] * w11;
#pragma unroll
        for (int c2 = 0; c2 < 32; c2++)
            acc[c2] = fmaf(v, s_w4[c2][c], acc[c2]);
    }

    float s = __ldg(b5);
#pragma unroll
    for (int c2 = 0; c2 < 32; c2++)
        s = fmaf(fmaxf(acc[c2], 0.0f), s_w5[c2], s);
    s = fmaxf(s, 0.0f);

    atomicMax((int*)out + (size_t)b * 147456 + oy * 384 + ox, __float_as_int(s));
}

// ---------------- host-side launch helpers ----------------------------------
static inline int cdiv(int a, int b) { return (a + b - 1) / b; }

static float* s_wbuf = nullptr;
static uint4* s_wq = nullptr;

// mma path
static void run_conv_mma(const float* in, const float* w, const float* b, float* out,
                         int N, int Cin, int Hin, int Win, int Cout,
                         int K, int stride, int pad, bool relu) {
    int Hout = (Hin + 2 * pad - K) / stride + 1;
    int Wout = (Win + 2 * pad - K) / stride + 1;
    int K2 = K * K;
    int chunks = cdiv(Cin, 16);
    int ksteps = chunks * K2;

    int NTv = (Cout >= 64) ? 8 : 4;
    int cotiles = cdiv(Cout, NTv * 8);
    int ntiles = cotiles * NTv;

    int wtotal = ksteps * ntiles * 32;
    wq_kernel<<<cdiv(wtotal, 256), 256>>>(w, s_wq, Cin, Cout, K2, ntiles, wtotal);

    int MRv = (stride == 1) ? 8 : 4;
    dim3 grid(cdiv(Wout, 32), cdiv(Hout, MRv), N * cotiles);
    int rl = relu ? 1 : 0;
    if (stride == 2) {
        conv_mma<3, 2, 8, 4><<<grid, 256>>>(in, s_wq, b, out, N, Cin, Hin, Win, Cout, Hout, Wout, pad, rl, cotiles, chunks, ntiles);
    } else if (NTv == 8) {
        if (K == 7)      conv_mma<7, 1, 8, 8><<<grid, 256>>>(in, s_wq, b, out, N, Cin, Hin, Win, Cout, Hout, Wout, pad, rl, cotiles, chunks, ntiles);
        else if (K == 5) conv_mma<5, 1, 8, 8><<<grid, 256>>>(in, s_wq, b, out, N, Cin, Hin, Win, Cout, Hout, Wout, pad, rl, cotiles, chunks, ntiles);
        else if (K == 3) conv_mma<3, 1, 8, 8><<<grid, 256>>>(in, s_wq, b, out, N, Cin, Hin, Win, Cout, Hout, Wout, pad, rl, cotiles, chunks, ntiles);
        else             conv_mma<1, 1, 8, 8><<<grid, 256>>>(in, s_wq, b, out, N, Cin, Hin, Win, Cout, Hout, Wout, pad, rl, cotiles, chunks, ntiles);
    } else {
        conv_mma<1, 1, 4, 8><<<grid, 256>>>(in, s_wq, b, out, N, Cin, Hin, Win, Cout, Hout, Wout, pad, rl, cotiles, chunks, ntiles);
    }
}

// scalar path (fw1 only)
static void run_conv_scalar(const float* in, const float* w, const float* b, float* out,
                            int N, int Cin, int Hin, int Win, int Cout,
                            int K, int stride, int pad, bool relu) {
    int Hout = (Hin + 2 * pad - K) / stride + 1;
    int Wout = (Win + 2 * pad - K) / stride + 1;
    int cotiles = cdiv(Cout, 32);
    int Co_pad = cotiles * 32;
    int K2 = K * K;

    int wtotal = Cin * K2 * Co_pad;
    wtrans_kernel<<<cdiv(wtotal, 256), 256>>>(w, s_wbuf, Cin, Cout, Co_pad, K2, wtotal);

    dim3 grid(cdiv(Wout, 32), cdiv(Hout, 4), N * cotiles);
    int rl = relu ? 1 : 0;
    conv_tiled2<7, 2><<<grid, 256>>>(in, s_wbuf, b, out, N, Cin, Hin, Win, Cout, Co_pad, Hout, Wout, pad, rl, cotiles);
}

extern "C" void kernel_launch(void* const* d_in, const int* in_sizes, int n_in,
                              void* d_out, int out_size) {
    const float* images = (const float*)d_in[0];
    const float* tlbrs  = (const float*)d_in[1];
    const float* fw1 = (const float*)d_in[2];
    const float* fw2 = (const float*)d_in[3];
    const float* fw3 = (const float*)d_in[4];
    const float* fw4 = (const float*)d_in[5];
    const float* rw1 = (const float*)d_in[6];
    const float* rb1 = (const float*)d_in[7];
    const float* rw2 = (const float*)d_in[8];
    const float* rb2 = (const float*)d_in[9];
    const float* rw3 = (const float*)d_in[10];
    const float* rb3 = (const float*)d_in[11];
    const float* rw4 = (const float*)d_in[12];
    const float* rb4 = (const float*)d_in[13];
    const float* rw5 = (const float*)d_in[14];
    const float* rb5 = (const float*)d_in[15];
    float* out = (float*)d_out;

    float *x1, *x2, *f3, *f4, *patches, *pf, *simtmp, *sims;
    float *r1, *u1, *r2, *u2, *r3;
    cudaGetSymbolAddress((void**)&x1, g_x1);
    cudaGetSymbolAddress((void**)&x2, g_x2);
    cudaGetSymbolAddress((void**)&f3, g_f3);
    cudaGetSymbolAddress((void**)&f4, g_f4);
    cudaGetSymbolAddress((void**)&patches, g_patches);
    cudaGetSymbolAddress((void**)&pf, g_pf);
    cudaGetSymbolAddress((void**)&simtmp, g_simtmp);
    cudaGetSymbolAddress((void**)&sims, g_sims);
    cudaGetSymbolAddress((void**)&r1, g_r1);
    cudaGetSymbolAddress((void**)&u1, g_u1);
    cudaGetSymbolAddress((void**)&r2, g_r2);
    cudaGetSymbolAddress((void**)&u2, g_u2);
    cudaGetSymbolAddress((void**)&r3, g_r3);
    cudaGetSymbolAddress((void**)&s_wbuf, g_wbuf);
    cudaGetSymbolAddress((void**)&s_wq, g_wq);

    // box metadata
    meta_kernel<<<1, 1>>>(tlbrs);

    // backbone
    run_conv_scalar(images, fw1, nullptr, x1, 2, 3, 384, 384, 64, 7, 2, 3, true);
    run_conv_mma(x1, fw2, nullptr, x2, 2, 64, 192, 192, 256, 3, 2, 1, true);
    run_conv_mma(x2, fw3, nullptr, f3, 2, 256, 96, 96, 512, 3, 2, 1, true);
    run_conv_mma(f3, fw4, nullptr, f4, 2, 512, 48, 48, 1024, 3, 2, 1, true);

    // similarity features (batched)
    const int SIMTMP_N = 2 * 2 * 3 * 3 * 2304;
    zero_kernel<<<cdiv(SIMTMP_N, 256), 256>>>(simtmp, SIMTMP_N);

    {   // L = 0 (f3: C=512, F=48)
        int C = 512, F = 48, L = 0;
        int te = NB * NP * C * 576;
        extract_patches_all<<<cdiv(te, 256), 256>>>(f3, patches, C, F, L);
        int tr = NB * 3 * NP * C * 1024;
        resize_pf_all<<<cdiv(tr, 256), 256>>>(patches, pf, C, L);
        int nchunks = 32, cpc = C / 32;
        sim_tiled<<<6 * nchunks, 256>>>(f3, pf, simtmp, C, F, L, nchunks, cpc);
    }
    {   // L = 1 (f4: C=1024, F=24)
        int C = 1024, F = 24, L = 1;
        int te = NB * NP * C * 576;
        extract_patches_all<<<cdiv(te, 256), 256>>>(f4, patches, C, F, L);
        int tr = NB * 3 * NP * C * 1024;
        resize_pf_all<<<cdiv(tr, 256), 256>>>(patches, pf, C, L);
        int nchunks = 32, cpc = C / 32;
        sim_tiled<<<6 * nchunks, 256>>>(f4, pf, simtmp, C, F, L, nchunks, cpc);
    }
    {
        int ts = NB * 2 * 3 * NP * 2304;
        sim_resize_all<<<cdiv(ts, 256), 256>>>(simtmp, sims);
    }

    // regressor
    run_conv_mma(sims, rw1, rb1, r1, 6, 6, 48, 48, 196, 7, 1, 3, true);
    upsample_kernel<<<cdiv(6 * 196 * 96 * 96, 256), 256>>>(r1, u1, 6 * 196, 48, 48);
    run_conv_mma(u1, rw2, rb2, r2, 6, 196, 96, 96, 128, 5, 1, 2, true);
    upsample_kernel<<<cdiv(6 * 128 * 192 * 192, 256), 256>>>(r2, u2, 6 * 128, 96, 96);
    run_conv_mma(u2, rw3, rb3, r3, 6, 128, 192, 192, 64, 3, 1, 1, true);

    // fused: upsample(r3) -> rw4 -> relu -> rw5 -> relu -> max over P
    zero_kernel<<<cdiv(NB * 147456, 256), 256>>>(out, NB * 147456);
    {
        dim3 grid(24, 24, 6);
        tail_fused<<<grid, 256>>>(r3, rw4, rb4, rw5, rb5, out);
    }
}

// round 13
// speedup vs baseline: 1.5563x; 1.5563x over previous
#include <cuda_runtime.h>
#include <cuda_bf16.h>
#include <math.h>

// ============================================================================
// FamNet pipeline. bf16 split mma convs (round-11 tiling) + fused tail.
// ============================================================================

#define NB 2
#define NP 3

// ---------------- device scratch (no allocations allowed) -------------------
__device__ float g_x1[2 * 64 * 192 * 192];
__device__ float g_x2[2 * 256 * 96 * 96];
__device__ float g_f3[2 * 512 * 48 * 48];
__device__ float g_f4[2 * 1024 * 24 * 24];
__device__ float g_patches[2 * 3 * 1024 * 576];
__device__ float g_pf[2 * 3 * 3 * 1024 * 1024];
__device__ float g_simtmp[2 * 2 * 3 * 3 * 2304];
__device__ float g_sims[2 * 3 * 6 * 48 * 48];
__device__ float g_r1[6 * 196 * 48 * 48];
__device__ float g_u1[6 * 196 * 96 * 96];
__device__ float g_r2[6 * 128 * 96 * 96];
__device__ float g_u2[6 * 128 * 192 * 192];
__device__ float g_r3[6 * 64 * 192 * 192];
__device__ float g_wbuf[64 * 49 * 64];                // scalar-path weights (fw1 only)
__device__ uint4 g_wq[1200000];                       // mma-path weights

// ---------------- box / scale metadata --------------------------------------
__device__ int g_tl[2][2][3][2];
__device__ int g_crop[2][2][3][2];
__device__ int g_PH[2][2], g_PW[2][2];
__device__ int g_PHs[2][2][3], g_PWs[2][2][3];

__global__ void meta_kernel(const float* __restrict__ tlbrs) {
    if (threadIdx.x != 0 || blockIdx.x != 0) return;
    const double scales[3] = {1.0, 0.9, 1.1};
    for (int b = 0; b < NB; b++) {
        for (int L = 0; L < 2; L++) {
            int F = (L == 0) ? 48 : 24;
            float inv = (float)F / 384.0f;
            int maxh = 0, maxw = 0;
            for (int p = 0; p < NP; p++) {
                const float* v = tlbrs + (b * NP + p) * 4;
                float sct = v[0] * inv, scl = v[1] * inv;
                float scb = v[2] * inv, scr = v[3] * inv;
                int top = (int)floorf(sct); if (top < 0) top = 0;
                int left = (int)floorf(scl); if (left < 0) left = 0;
                int bot = (int)ceilf(scb) + 1; if (bot > F) bot = F;
                int right = (int)ceilf(scr) + 1; if (right > F) right = F;
                g_tl[b][L][p][0] = top;  g_tl[b][L][p][1] = left;
                g_crop[b][L][p][0] = bot - top;  g_crop[b][L][p][1] = right - left;
                if (bot - top > maxh) maxh = bot - top;
                if (right - left > maxw) maxw = right - left;
            }
            g_PH[b][L] = maxh; g_PW[b][L] = maxw;
            for (int s = 0; s < 3; s++) {
                int ph = (int)ceil((double)maxh * scales[s]);
                int pw = (int)ceil((double)maxw * scales[s]);
                if (ph < 1) ph = maxh;
                if (pw < 1) pw = maxw;
                g_PHs[b][L][s] = ph; g_PWs[b][L][s] = pw;
            }
        }
    }
}

// ---------------- helpers ----------------------------------------------------
__device__ __forceinline__ unsigned pk(float a, float b) {
    unsigned ha = (unsigned)__bfloat16_as_ushort(__float2bfloat16_rn(a));
    unsigned hb = (unsigned)__bfloat16_as_ushort(__float2bfloat16_rn(b));
    return ha | (hb << 16);
}
__device__ __forceinline__ float bhi(float v) {
    return __bfloat162float(__float2bfloat16_rn(v));
}

#define MMA(d, a, bb0, bb1)                                                       \
    asm volatile("mma.sync.aligned.m16n8k16.row.col.f32.bf16.bf16.f32 "           \
                 "{%0,%1,%2,%3},{%4,%5,%6,%7},{%8,%9},{%0,%1,%2,%3};"             \
                 : "+f"(d[0]), "+f"(d[1]), "+f"(d[2]), "+f"(d[3])                 \
                 : "r"(a[0]), "r"(a[1]), "r"(a[2]), "r"(a[3]), "r"(bb0), "r"(bb1))

// ---------------- mma weight transform ---------------------------------------
__global__ void wq_kernel(const float* __restrict__ wt, uint4* __restrict__ wq,
                          int Cin, int Cout, int K2, int ntiles, int total) {
    int idx = blockIdx.x * blockDim.x + threadIdx.x;
    if (idx >= total) return;
    int lane = idx & 31;
    int nt = (idx >> 5) % ntiles;
    int t = idx / (32 * ntiles);
    int chunk = t / K2, tl = t - chunk * K2;
    int n = nt * 8 + (lane >> 2);
    int kf0 = (lane & 3) * 2;

    float w[4], whi[4];
#pragma unroll
    for (int j = 0; j < 4; j++) {
        int kf = kf0 + (j >> 1) * 8 + (j & 1);
        int ci = chunk * 16 + kf;
        w[j] = (ci < Cin && n < Cout) ? __ldg(wt + ((size_t)n * Cin + ci) * K2 + tl) : 0.0f;
        whi[j] = bhi(w[j]);
    }
    uint4 o;
    o.x = pk(whi[0], whi[1]);
    o.y = pk(whi[2], whi[3]);
    o.z = pk(w[0] - whi[0], w[1] - whi[1]);
    o.w = pk(w[2] - whi[2], w[3] - whi[3]);
    wq[idx] = o;
}

// ---------------- mma conv: 32x4 px x (NT*8) couts (round-11 winner) ---------
template <int K, int STRIDE, int NT>
__global__ void __launch_bounds__(256)
conv_mma(const float* __restrict__ in, const uint4* __restrict__ wq,
         const float* __restrict__ bias, float* __restrict__ out,
         int N, int Cin, int Hin, int Win, int Cout, int Hout, int Wout,
         int pad, int relu, int cotiles, int chunks, int ntiles) {
    constexpr int K2 = K * K;
    constexpr int IH = 3 * STRIDE + K;
    constexpr int IW = 31 * STRIDE + K;
    constexpr int NPX = IH * IW;

    __shared__ unsigned s_hi[NPX][8];
    __shared__ unsigned s_lo[NPX][8];

    const int tid = threadIdx.x;
    const int lane = tid & 31;
    const int wm = tid >> 5;

    const int bx = blockIdx.x, by = blockIdx.y;
    const int n = blockIdx.z / cotiles;
    const int co0 = (blockIdx.z % cotiles) * (NT * 8);

    const int ix0 = bx * 32 * STRIDE - pad;
    const int iy0 = by * 4 * STRIDE - pad;

    const int y = wm >> 1;
    const int r = lane >> 2;
    const int xA = ((wm & 1) << 4) + r;
    const int pcL = lane & 3;
    const int c0 = pcL * 2;

    float acc[NT][4];
#pragma unroll
    for (int i = 0; i < NT; i++)
#pragma unroll
        for (int j = 0; j < 4; j++) acc[i][j] = 0.0f;

    const size_t in_n = (size_t)n * Cin * Hin * Win;
    const size_t HW = (size_t)Hin * Win;

    for (int chunk = 0; chunk < chunks; chunk++) {
        for (int i = tid; i < 8 * NPX; i += 256) {
            int pc = i / NPX;
            int rem = i - pc * NPX;
            int rr = rem / IW, cc = rem - rr * IW;
            int gy = iy0 + rr, gx = ix0 + cc;
            int ci0 = chunk * 16 + pc * 2;
            float f0 = 0.0f, f1 = 0.0f;
            if ((unsigned)gy < (unsigned)Hin && (unsigned)gx < (unsigned)Win) {
                const float* p = in + in_n + (size_t)gy * Win + gx;
                if (ci0 < Cin)     f0 = __ldg(p + (size_t)ci0 * HW);
                if (ci0 + 1 < Cin) f1 = __ldg(p + (size_t)(ci0 + 1) * HW);
            }
            float h0 = bhi(f0), h1 = bhi(f1);
            int sw = (pc + rem) & 7;
            s_hi[rem][sw] = pk(h0, h1);
            s_lo[rem][sw] = pk(f0 - h0, f1 - h1);
        }
        __syncthreads();

#pragma unroll 1
        for (int tl = 0; tl < K2; tl++) {
            int kh = tl / K, kw = tl - kh * K;
            int pixA = (y * STRIDE + kh) * IW + kw + xA * STRIDE;
            int pixB = pixA + 8 * STRIDE;

            unsigned ahi[4], alo[4];
            ahi[0] = s_hi[pixA][(pcL + pixA) & 7];
            ahi[1] = s_hi[pixB][(pcL + pixB) & 7];
            ahi[2] = s_hi[pixA][(pcL + 4 + pixA) & 7];
            ahi[3] = s_hi[pixB][(pcL + 4 + pixB) & 7];
            alo[0] = s_lo[pixA][(pcL + pixA) & 7];
            alo[1] = s_lo[pixB][(pcL + pixB) & 7];
            alo[2] = s_lo[pixA][(pcL + 4 + pixA) & 7];
            alo[3] = s_lo[pixB][(pcL + 4 + pixB) & 7];

            int tg = chunk * K2 + tl;
            const uint4* wrow = wq + ((size_t)tg * ntiles + (co0 >> 3)) * 32 + lane;
#pragma unroll
            for (int nt = 0; nt < NT; nt++) {
                uint4 wv = __ldg(wrow + nt * 32);
                MMA(acc[nt], ahi, wv.x, wv.y);   // hi*hi
                MMA(acc[nt], ahi, wv.z, wv.w);   // hi*lo
                MMA(acc[nt], alo, wv.x, wv.y);   // lo*hi
            }
        }
        __syncthreads();
    }

    const int oy = by * 4 + y;
    if (oy >= Hout) return;
#pragma unroll
    for (int half = 0; half < 2; half++) {
        int ox = bx * 32 + xA + half * 8;
        if (ox >= Wout) continue;
#pragma unroll
        for (int nt = 0; nt < NT; nt++) {
#pragma unroll
            for (int e = 0; e < 2; e++) {
                int co = co0 + nt * 8 + c0 + e;
                if (co >= Cout) continue;
                float v = acc[nt][half * 2 + e];
                if (bias) v += __ldg(bias + co);
                if (relu) v = fmaxf(v, 0.0f);
                out[(((size_t)n * Cout + co) * Hout + oy) * Wout + ox] = v;
            }
        }
    }
}

// ---------------- scalar weight transpose (fw1 only) -------------------------
__global__ void wtrans_kernel(const float* __restrict__ wt, float* __restrict__ wbuf,
                              int Cin, int Cout, int Co_pad, int K2, int total) {
    int idx = blockIdx.x * blockDim.x + threadIdx.x;
    if (idx >= total) return;
    int co = idx % Co_pad;
    int t = idx / Co_pad;
    int kk = t % K2;
    int ci = t / K2;
    wbuf[idx] = (co < Cout) ? __ldg(wt + ((size_t)co * Cin + ci) * K2 + kk) : 0.0f;
}

// ---------------- scalar conv (fw1 only: K=7, S=2) ---------------------------
template <int K, int STRIDE>
__global__ void conv_tiled2(const float* __restrict__ in, const float* __restrict__ wbuf,
                            const float* __restrict__ bias, float* __restrict__ out,
                            int N, int Cin, int Hin, int Win,
                            int Cout, int Co_pad, int Hout, int Wout,
                            int pad, int relu, int cotiles) {
    constexpr int K2 = K * K;
    constexpr int IH = 3 * STRIDE + K;
    constexpr int IW = 31 * STRIDE + K;

    __shared__ float s_in[IH * IW];
    __shared__ float4 s_w[K2 * 8];

    const int tid = threadIdx.x;
    const int tx = tid & 15;
    const int ty = (tid >> 4) & 1;
    const int tc = tid >> 5;

    const int bx = blockIdx.x, by = blockIdx.y;
    const int n   = blockIdx.z / cotiles;
    const int co0 = (blockIdx.z % cotiles) * 32;

    const int ix0 = bx * 32 * STRIDE - pad;
    const int iy0 = by * 4 * STRIDE - pad;

    float acc[2][2][4] = {};
    const size_t in_n = (size_t)n * Cin * Hin * Win;

    for (int ci = 0; ci < Cin; ci++) {
        __syncthreads();
        const float* ip = in + in_n + (size_t)ci * Hin * Win;
#pragma unroll 2
        for (int i = tid; i < IH * IW; i += 256) {
            int r = i / IW, c = i - r * IW;
            int gy = iy0 + r, gx = ix0 + c;
            float v = 0.0f;
            if ((unsigned)gy < (unsigned)Hin && (unsigned)gx < (unsigned)Win)
                v = __ldg(ip + (size_t)gy * Win + gx);
            s_in[i] = v;
        }
        const float* wp = wbuf + (size_t)ci * K2 * Co_pad + co0;
#pragma unroll 2
        for (int i = tid; i < K2 * 32; i += 256) {
            int kk = i >> 5, c = i & 31;
            ((float*)s_w)[i] = __ldg(wp + kk * Co_pad + c);
        }
        __syncthreads();

#pragma unroll
        for (int kh = 0; kh < K; kh++) {
#pragma unroll
            for (int kw = 0; kw < K; kw++) {
                float4 w = s_w[(kh * K + kw) * 8 + tc];
                float iv[2][2];
#pragma unroll
                for (int yy = 0; yy < 2; yy++)
#pragma unroll
                    for (int xx = 0; xx < 2; xx++)
                        iv[yy][xx] = s_in[((2 * ty + yy) * STRIDE + kh) * IW
                                          + (2 * tx + xx) * STRIDE + kw];
#pragma unroll
                for (int yy = 0; yy < 2; yy++)
#pragma unroll
                    for (int xx = 0; xx < 2; xx++) {
                        acc[yy][xx][0] = fmaf(iv[yy][xx], w.x, acc[yy][xx][0]);
                        acc[yy][xx][1] = fmaf(iv[yy][xx], w.y, acc[yy][xx][1]);
                        acc[yy][xx][2] = fmaf(iv[yy][xx], w.z, acc[yy][xx][2]);
                        acc[yy][xx][3] = fmaf(iv[yy][xx], w.w, acc[yy][xx][3]);
                    }
            }
        }
    }

    const int ox = bx * 32 + 2 * tx;
    if (ox >= Wout) return;
#pragma unroll
    for (int c = 0; c < 4; c++) {
        int co = co0 + tc * 4 + c;
        if (co >= Cout) continue;
        float bv = bias ? __ldg(bias + co) : 0.0f;
#pragma unroll
        for (int yy = 0; yy < 2; yy++) {
            int oy = by * 4 + 2 * ty + yy;
            if (oy >= Hout) continue;
            float v0 = acc[yy][0][c] + bv;
            float v1 = acc[yy][1][c] + bv;
            if (relu) { v0 = fmaxf(v0, 0.0f); v1 = fmaxf(v1, 0.0f); }
            *(float2*)(out + (((size_t)n * Cout + co) * Hout + oy) * Wout + ox)
                = make_float2(v0, v1);
        }
    }
}

// ---------------- patch extraction -------------------------------------------
__global__ void extract_patches_all(const float* __restrict__ fmbase, float* __restrict__ patches,
                                    int C, int F, int L) {
    int idx = blockIdx.x * blockDim.x + threadIdx.x;
    int total = NB * NP * C * 576;
    if (idx >= total) return;
    int ox = idx % 24;
    int oy = (idx / 24) % 24;
    int c = (idx / 576) % C;
    int p = (idx / (576 * C)) % NP;
    int b = idx / (576 * C * NP);
    int PH = g_PH[b][L], PW = g_PW[b][L];
    if (oy >= PH || ox >= PW) return;
    int top = g_tl[b][L][p][0], left = g_tl[b][L][p][1];
    int h = g_crop[b][L][p][0], w = g_crop[b][L][p][1];

    float sy = ((float)oy + 0.5f) * ((float)h / (float)PH) - 0.5f;
    if (sy < 0.0f) sy = 0.0f;
    float sx = ((float)ox + 0.5f) * ((float)w / (float)PW) - 0.5f;
    if (sx < 0.0f) sx = 0.0f;
    int y0 = (int)sy; float ty = sy - (float)y0;
    int x0 = (int)sx; float tx = sx - (float)x0;
    if (y0 > h - 1) { y0 = h - 1; ty = 0.0f; }
    if (x0 > w - 1) { x0 = w - 1; tx = 0.0f; }
    int y1 = min(y0 + 1, h - 1);
    int x1 = min(x0 + 1, w - 1);

    const float* base = fmbase + (size_t)b * C * F * F + ((size_t)c * F + top) * F + left;
    float v00 = base[y0 * F + x0], v01 = base[y0 * F + x1];
    float v10 = base[y1 * F + x0], v11 = base[y1 * F + x1];
    float val = v00 * (1.0f - ty) * (1.0f - tx) + v01 * (1.0f - ty) * tx
              + v10 * ty * (1.0f - tx) + v11 * ty * tx;
    patches[((size_t)((b * NP + p) * C + c)) * 576 + oy * 24 + ox] = val;
}

__global__ void resize_pf_all(const float* __restrict__ patches, float* __restrict__ pf,
                              int C, int L) {
    int idx = blockIdx.x * blockDim.x + threadIdx.x;
    int total = NB * 3 * NP * C * 1024;
    if (idx >= total) return;
    int ox = idx & 31;
    int oy = (idx >> 5) & 31;
    int c = (idx >> 10) % C;
    int rest = idx / (1024 * C);
    int p = rest % NP;
    int s = (rest / NP) % 3;
    int b = rest / (NP * 3);

    int PHs = g_PHs[b][L][s], PWs = g_PWs[b][L][s];
    if (oy >= PHs || ox >= PWs) return;
    int PH = g_PH[b][L], PW = g_PW[b][L];

    float sy = ((float)oy + 0.5f) * ((float)PH / (float)PHs) - 0.5f;
    if (sy < 0.0f) sy = 0.0f;
    float sx = ((float)ox + 0.5f) * ((float)PW / (float)PWs) - 0.5f;
    if (sx < 0.0f) sx = 0.0f;
    int y0 = (int)sy; float ty = sy - (float)y0;
    int x0 = (int)sx; float tx = sx - (float)x0;
    if (y0 > PH - 1) { y0 = PH - 1; ty = 0.0f; }
    if (x0 > PW - 1) { x0 = PW - 1; tx = 0.0f; }
    int y1 = min(y0 + 1, PH - 1);
    int x1 = min(x0 + 1, PW - 1);

    const float* base = patches + ((size_t)((b * NP + p) * C + c)) * 576;
    float v00 = base[y0 * 24 + x0], v01 = base[y0 * 24 + x1];
    float v10 = base[y1 * 24 + x0], v11 = base[y1 * 24 + x1];
    float val = v00 * (1.0f - ty) * (1.0f - tx) + v01 * (1.0f - ty) * tx
              + v10 * ty * (1.0f - tx) + v11 * ty * tx;
    pf[((size_t)(((b * 3 + s) * NP + p) * C + c) << 10) + oy * 32 + ox] = val;
}

__global__ void zero_kernel(float* __restrict__ buf, int n) {
    int idx = blockIdx.x * blockDim.x + threadIdx.x;
    if (idx < n) buf[idx] = 0.0f;
}

// ---------------- tiled correlation ------------------------------------------
__global__ void __launch_bounds__(256)
sim_tiled(const float* __restrict__ fmbase, const float* __restrict__ pf,
          float* __restrict__ simtmp, int C, int F, int L, int nchunks, int cpc) {
    __shared__ float s_fm[63 * 64];
    __shared__ float s_pf[3][16 * 32];

    const int tid = threadIdx.x;
    const int tx = tid & 15, ty = tid >> 4;

    int chunk = blockIdx.x % nchunks;
    int bs = blockIdx.x / nchunks;
    int b = bs / 3, s = bs % 3;

    int PHs = g_PHs[b][L][s], PWs = g_PWs[b][L][s];
    int padT = PHs >> 1, padL = PWs >> 1;

    const int FF = F * F;
    const float* fm = fmbase + (size_t)b * C * FF;
    const float* pfb = pf + ((size_t)(bs * NP) * C << 10);
    int c0 = chunk * cpc;

    float acc[3][3][3];
#pragma unroll
    for (int p = 0; p < 3; p++)
#pragma unroll
        for (int ry = 0; ry < 3; ry++)
#pragma unroll
            for (int rx = 0; rx < 3; rx++) acc[p][ry][rx] = 0.0f;

    const int iy0 = -padT, ix0 = -padL;
    const int pfrows = PHs * 32;

    for (int c = c0; c < c0 + cpc; c++) {
        __syncthreads();
        const float* fmc = fm + (size_t)c * FF;
        for (int i = tid; i < 63 * 64; i += 256) {
            int r = i >> 6, cc = i & 63;
            int gy = iy0 + r, gx = ix0 + cc;
            float v = 0.0f;
            if ((unsigned)gy < (unsigned)F && (unsigned)gx < (unsigned)F)
                v = __ldg(fmc + gy * F + gx);
            s_fm[i] = v;
        }
        for (int i = tid; i < 3 * pfrows; i += 256) {
            int p = i / pfrows;
            int rem = i - p * pfrows;
            s_pf[p][rem] = __ldg(pfb + (((size_t)(p * C + c)) << 10) + rem);
        }
        __syncthreads();

        for (int i = 0; i < PHs; i++) {
            const float* fr = &s_fm[(ty + i) * 64 + tx];
            const float* p0 = &s_pf[0][i * 32];
            const float* p1 = &s_pf[1][i * 32];
            const float* p2 = &s_pf[2][i * 32];
            for (int j = 0; j < PWs; j++) {
                float w0 = p0[j], w1 = p1[j], w2 = p2[j];
                float v[3][3];
#pragma unroll
                for (int ry = 0; ry < 3; ry++)
#pragma unroll
                    for (int rx = 0; rx < 3; rx++)
                        v[ry][rx] = fr[(ry * 16) * 64 + rx * 16 + j];
#pragma unroll
                for (int ry = 0; ry < 3; ry++)
#pragma unroll
                    for (int rx = 0; rx < 3; rx++) {
                        acc[0][ry][rx] = fmaf(v[ry][rx], w0, acc[0][ry][rx]);
                        acc[1][ry][rx] = fmaf(v[ry][rx], w1, acc[1][ry][rx]);
                        acc[2][ry][rx] = fmaf(v[ry][rx], w2, acc[2][ry][rx]);
                    }
            }
        }
    }

#pragma unroll
    for (int p = 0; p < 3; p++) {
        float* dst = simtmp + (size_t)(((b * 2 + L) * 3 + s) * NP + p) * 2304;
#pragma unroll
        for (int ry = 0; ry < 3; ry++) {
            int y = ty + ry * 16;
            if (y >= F) continue;
#pragma unroll
            for (int rx = 0; rx < 3; rx++) {
                int x = tx + rx * 16;
                if (x >= F) continue;
                atomicAdd(dst + y * F + x, acc[p][ry][rx]);
            }
        }
    }
}

__global__ void sim_resize_all(const float* __restrict__ simtmp, float* __restrict__ sims) {
    int idx = blockIdx.x * blockDim.x + threadIdx.x;
    int total = NB * 2 * 3 * NP * 2304;
    if (idx >= total) return;
    int x = idx % 48;
    int y = (idx / 48) % 48;
    int p = (idx / 2304) % NP;
    int s = (idx / (2304 * NP)) % 3;
    int L = (idx / (2304 * NP * 3)) % 2;
    int b = idx / (2304 * NP * 3 * 2);
    int F = L ? 24 : 48;

    float sy = ((float)y + 0.5f) * ((float)F / 48.0f) - 0.5f;
    if (sy < 0.0f) sy = 0.0f;
    float sx = ((float)x + 0.5f) * ((float)F / 48.0f) - 0.5f;
    if (sx < 0.0f) sx = 0.0f;
    int y0 = (int)sy; float ty = sy - (float)y0;
    int x0 = (int)sx; float tx = sx - (float)x0;
    if (y0 > F - 1) { y0 = F - 1; ty = 0.0f; }
    if (x0 > F - 1) { x0 = F - 1; tx = 0.0f; }
    int y1 = min(y0 + 1, F - 1);
    int x1 = min(x0 + 1, F - 1);

    const float* base = simtmp + (size_t)(((b * 2 + L) * 3 + s) * NP + p) * 2304;
    float v00 = base[y0 * F + x0], v01 = base[y0 * F + x1];
    float v10 = base[y1 * F + x0], v11 = base[y1 * F + x1];
    float val = v00 * (1.0f - ty) * (1.0f - tx) + v01 * (1.0f - ty) * tx
              + v10 * ty * (1.0f - tx) + v11 * ty * tx;
    int ch = L * 3 + s;
    sims[((size_t)(b * NP + p) * 6 + ch) * 2304 + y * 48 + x] = val;
}

// ---------------- align-corners 2x bilinear upsample (u1, u2) ----------------
__global__ void upsample_kernel(const float* __restrict__ in, float* __restrict__ out,
                                int NC, int h, int w) {
    int H = 2 * h, W = 2 * w;
    int idx = blockIdx.x * blockDim.x + threadIdx.x;
    int total = NC * H * W;
    if (idx >= total) return;
    int ox = idx % W;
    int oy = (idx / W) % H;
    int nc = idx / (H * W);

    float stepy = (float)(h - 1) / (float)(H - 1);
    float stepx = (float)(w - 1) / (float)(W - 1);
    float py = (float)oy * stepy;
    float px = (float)ox * stepx;
    int y0 = (int)py; float ty = py - (float)y0;
    int x0 = (int)px; float tx = px - (float)x0;
    if (y0 > h - 1) { y0 = h - 1; ty = 0.0f; }
    if (x0 > w - 1) { x0 = w - 1; tx = 0.0f; }
    int y1 = min(y0 + 1, h - 1);
    int x1 = min(x0 + 1, w - 1);

    const float* ib = in + (size_t)nc * h * w;
    float v00 = ib[y0 * w + x0], v01 = ib[y0 * w + x1];
    float v10 = ib[y1 * w + x0], v11 = ib[y1 * w + x1];
    out[idx] = v00 * (1.0f - ty) * (1.0f - tx) + v01 * (1.0f - ty) * tx
             + v10 * ty * (1.0f - tx) + v11 * ty * tx;
}

// ---------------- fused: up2x(r3) -> rw4 1x1 relu -> rw5 1x1 relu -> max ----
__global__ void __launch_bounds__(256)
tail_fused(const float* __restrict__ r3, const float* __restrict__ w4,
           const float* __restrict__ b4, const float* __restrict__ w5,
           const float* __restrict__ b5, float* __restrict__ out) {
    __shared__ float s_r3[64][10][10];
    __shared__ float s_w4[32][64];
    __shared__ float s_w5[32];
    __shared__ float s_b4[32];

    const int tid = threadIdx.x;
    const int bp = blockIdx.z;
    const int b = bp / NP;
    const int ox0 = blockIdx.x * 16, oy0 = blockIdx.y * 16;
    const float f = 191.0f / 383.0f;

    int iy0 = (int)floorf((float)oy0 * f);
    int ix0 = (int)floorf((float)ox0 * f);

    for (int i = tid; i < 2048; i += 256)
        s_w4[i >> 6][i & 63] = __ldg(w4 + i);
    if (tid < 32) { s_w5[tid] = __ldg(w5 + tid); s_b4[tid] = __ldg(b4 + tid); }

    const float* src = r3 + (size_t)bp * 64 * 192 * 192;
    for (int i = tid; i < 64 * 100; i += 256) {
        int c = i / 100;
        int rem = i - c * 100;
        int ry = rem / 10, rx = rem - ry * 10;
        int gy = iy0 + ry, gx = ix0 + rx;
        float v = 0.0f;
        if (gy < 192 && gx < 192)
            v = __ldg(src + ((size_t)c * 192 + gy) * 192 + gx);
        s_r3[c][ry][rx] = v;
    }
    __syncthreads();

    const int ox = ox0 + (tid & 15);
    const int oy = oy0 + (tid >> 4);

    float py = (float)oy * f;
    float px = (float)ox * f;
    int y0 = (int)py; float ty = py - (float)y0;
    int x0 = (int)px; float tx = px - (float)x0;
    if (y0 > 191) { y0 = 191; ty = 0.0f; }
    if (x0 > 191) { x0 = 191; tx = 0.0f; }
    int y1 = min(y0 + 1, 191);
    int x1 = min(x0 + 1, 191);

    int ly = y0 - iy0, lx = x0 - ix0;
    int ly1 = y1 - iy0, lx1 = x1 - ix0;

    float w00 = (1.0f - ty) * (1.0f - tx), w01 = (1.0f - ty) * tx;
    float w10 = ty * (1.0f - tx), w11 = ty * tx;

    float acc[32];
#pragma unroll
    for (int c2 = 0; c2 < 32; c2++) acc[c2] = s_b4[c2];

    for (int c = 0; c < 64; c++) {
        float v = s_r3[c][ly][lx] * w00 + s_r3[c][ly][lx1] * w01
                + s_r3[c][ly1][lx] * w10 + s_r3[c][ly1][lx1] * w11;
#pragma unroll
        for (int c2 = 0; c2 < 32; c2++)
            acc[c2] = fmaf(v, s_w4[c2][c], acc[c2]);
    }

    float s = __ldg(b5);
#pragma unroll
    for (int c2 = 0; c2 < 32; c2++)
        s = fmaf(fmaxf(acc[c2], 0.0f), s_w5[c2], s);
    s = fmaxf(s, 0.0f);

    atomicMax((int*)out + (size_t)b * 147456 + oy * 384 + ox, __float_as_int(s));
}

// ---------------- host-side launch helpers ----------------------------------
static inline int cdiv(int a, int b) { return (a + b - 1) / b; }

static float* s_wbuf = nullptr;
static uint4* s_wq = nullptr;

// mma path
static void run_conv_mma(const float* in, const float* w, const float* b, float* out,
                         int N, int Cin, int Hin, int Win, int Cout,
                         int K, int stride, int pad, bool relu) {
    int Hout = (Hin + 2 * pad - K) / stride + 1;
    int Wout = (Win + 2 * pad - K) / stride + 1;
    int K2 = K * K;
    int chunks = cdiv(Cin, 16);
    int ksteps = chunks * K2;

    int NTv = (Cout >= 64) ? 8 : 4;
    int cotiles = cdiv(Cout, NTv * 8);
    int ntiles = cotiles * NTv;

    int wtotal = ksteps * ntiles * 32;
    wq_kernel<<<cdiv(wtotal, 256), 256>>>(w, s_wq, Cin, Cout, K2, ntiles, wtotal);

    dim3 grid(cdiv(Wout, 32), cdiv(Hout, 4), N * cotiles);
    int rl = relu ? 1 : 0;
    if (stride == 2) {
        conv_mma<3, 2, 8><<<grid, 256>>>(in, s_wq, b, out, N, Cin, Hin, Win, Cout, Hout, Wout, pad, rl, cotiles, chunks, ntiles);
    } else if (NTv == 8) {
        if (K == 7)      conv_mma<7, 1, 8><<<grid, 256>>>(in, s_wq, b, out, N, Cin, Hin, Win, Cout, Hout, Wout, pad, rl, cotiles, chunks, ntiles);
        else if (K == 5) conv_mma<5, 1, 8><<<grid, 256>>>(in, s_wq, b, out, N, Cin, Hin, Win, Cout, Hout, Wout, pad, rl, cotiles, chunks, ntiles);
        else if (K == 3) conv_mma<3, 1, 8><<<grid, 256>>>(in, s_wq, b, out, N, Cin, Hin, Win, Cout, Hout, Wout, pad, rl, cotiles, chunks, ntiles);
        else             conv_mma<1, 1, 8><<<grid, 256>>>(in, s_wq, b, out, N, Cin, Hin, Win, Cout, Hout, Wout, pad, rl, cotiles, chunks, ntiles);
    } else {
        conv_mma<1, 1, 4><<<grid, 256>>>(in, s_wq, b, out, N, Cin, Hin, Win, Cout, Hout, Wout, pad, rl, cotiles, chunks, ntiles);
    }
}

// scalar path (fw1 only)
static void run_conv_scalar(const float* in, const float* w, const float* b, float* out,
                            int N, int Cin, int Hin, int Win, int Cout,
                            int K, int stride, int pad, bool relu) {
    int Hout = (Hin + 2 * pad - K) / stride + 1;
    int Wout = (Win + 2 * pad - K) / stride + 1;
    int cotiles = cdiv(Cout, 32);
    int Co_pad = cotiles * 32;
    int K2 = K * K;

    int wtotal = Cin * K2 * Co_pad;
    wtrans_kernel<<<cdiv(wtotal, 256), 256>>>(w, s_wbuf, Cin, Cout, Co_pad, K2, wtotal);

    dim3 grid(cdiv(Wout, 32), cdiv(Hout, 4), N * cotiles);
    int rl = relu ? 1 : 0;
    conv_tiled2<7, 2><<<grid, 256>>>(in, s_wbuf, b, out, N, Cin, Hin, Win, Cout, Co_pad, Hout, Wout, pad, rl, cotiles);
}

extern "C" void kernel_launch(void* const* d_in, const int* in_sizes, int n_in,
                              void* d_out, int out_size) {
    const float* images = (const float*)d_in[0];
    const float* tlbrs  = (const float*)d_in[1];
    const float* fw1 = (const float*)d_in[2];
    const float* fw2 = (const float*)d_in[3];
    const float* fw3 = (const float*)d_in[4];
    const float* fw4 = (const float*)d_in[5];
    const float* rw1 = (const float*)d_in[6];
    const float* rb1 = (const float*)d_in[7];
    const float* rw2 = (const float*)d_in[8];
    const float* rb2 = (const float*)d_in[9];
    const float* rw3 = (const float*)d_in[10];
    const float* rb3 = (const float*)d_in[11];
    const float* rw4 = (const float*)d_in[12];
    const float* rb4 = (const float*)d_in[13];
    const float* rw5 = (const float*)d_in[14];
    const float* rb5 = (const float*)d_in[15];
    float* out = (float*)d_out;

    float *x1, *x2, *f3, *f4, *patches, *pf, *simtmp, *sims;
    float *r1, *u1, *r2, *u2, *r3;
    cudaGetSymbolAddress((void**)&x1, g_x1);
    cudaGetSymbolAddress((void**)&x2, g_x2);
    cudaGetSymbolAddress((void**)&f3, g_f3);
    cudaGetSymbolAddress((void**)&f4, g_f4);
    cudaGetSymbolAddress((void**)&patches, g_patches);
    cudaGetSymbolAddress((void**)&pf, g_pf);
    cudaGetSymbolAddress((void**)&simtmp, g_simtmp);
    cudaGetSymbolAddress((void**)&sims, g_sims);
    cudaGetSymbolAddress((void**)&r1, g_r1);
    cudaGetSymbolAddress((void**)&u1, g_u1);
    cudaGetSymbolAddress((void**)&r2, g_r2);
    cudaGetSymbolAddress((void**)&u2, g_u2);
    cudaGetSymbolAddress((void**)&r3, g_r3);
    cudaGetSymbolAddress((void**)&s_wbuf, g_wbuf);
    cudaGetSymbolAddress((void**)&s_wq, g_wq);

    // box metadata
    meta_kernel<<<1, 1>>>(tlbrs);

    // backbone
    run_conv_scalar(images, fw1, nullptr, x1, 2, 3, 384, 384, 64, 7, 2, 3, true);
    run_conv_mma(x1, fw2, nullptr, x2, 2, 64, 192, 192, 256, 3, 2, 1, true);
    run_conv_mma(x2, fw3, nullptr, f3, 2, 256, 96, 96, 512, 3, 2, 1, true);
    run_conv_mma(f3, fw4, nullptr, f4, 2, 512, 48, 48, 1024, 3, 2, 1, true);

    // similarity features (batched)
    const int SIMTMP_N = 2 * 2 * 3 * 3 * 2304;
    zero_kernel<<<cdiv(SIMTMP_N, 256), 256>>>(simtmp, SIMTMP_N);

    {   // L = 0 (f3: C=512, F=48)
        int C = 512, F = 48, L = 0;
        int te = NB * NP * C * 576;
        extract_patches_all<<<cdiv(te, 256), 256>>>(f3, patches, C, F, L);
        int tr = NB * 3 * NP * C * 1024;
        resize_pf_all<<<cdiv(tr, 256), 256>>>(patches, pf, C, L);
        int nchunks = 32, cpc = C / 32;
        sim_tiled<<<6 * nchunks, 256>>>(f3, pf, simtmp, C, F, L, nchunks, cpc);
    }
    {   // L = 1 (f4: C=1024, F=24)
        int C = 1024, F = 24, L = 1;
        int te = NB * NP * C * 576;
        extract_patches_all<<<cdiv(te, 256), 256>>>(f4, patches, C, F, L);
        int tr = NB * 3 * NP * C * 1024;
        resize_pf_all<<<cdiv(tr, 256), 256>>>(patches, pf, C, L);
        int nchunks = 32, cpc = C / 32;
        sim_tiled<<<6 * nchunks, 256>>>(f4, pf, simtmp, C, F, L, nchunks, cpc);
    }
    {
        int ts = NB * 2 * 3 * NP * 2304;
        sim_resize_all<<<cdiv(ts, 256), 256>>>(simtmp, sims);
    }

    // regressor
    run_conv_mma(sims, rw1, rb1, r1, 6, 6, 48, 48, 196, 7, 1, 3, true);
    upsample_kernel<<<cdiv(6 * 196 * 96 * 96, 256), 256>>>(r1, u1, 6 * 196, 48, 48);
    run_conv_mma(u1, rw2, rb2, r2, 6, 196, 96, 96, 128, 5, 1, 2, true);
    upsample_kernel<<<cdiv(6 * 128 * 192 * 192, 256), 256>>>(r2, u2, 6 * 128, 96, 96);
    run_conv_mma(u2, rw3, rb3, r3, 6, 128, 192, 192, 64, 3, 1, 1, true);

    // fused: upsample(r3) -> rw4 -> relu -> rw5 -> relu -> max over P
    zero_kernel<<<cdiv(NB * 147456, 256), 256>>>(out, NB * 147456);
    {
        dim3 grid(24, 24, 6);
        tail_fused<<<grid, 256>>>(r3, rw4, rb4, rw5, rb5, out);
    }
}